// round 11
// baseline (speedup 1.0000x reference)
#include <cuda_runtime.h>
#include <cuda_fp16.h>
#include <cstdint>

#define N_  2
#define C_  128
#define D_  32
#define H_  64
#define W_  64
#define R_  256
#define PD  4
#define PH  7
#define PW  7
#define HW_ (H_ * W_)
#define DHW (D_ * H_ * W_)
#define NCELL (PH * PW)           // 49
#define TAPCAP 68                 // 64 + pad

// 64 MB static scratch: NDHWC features quantized to fp16
__device__ __half g_feat_t[(size_t)N_ * DHW * C_];

// ---------------------------------------------------------------------------
// Transpose NCDHW fp32 -> NDHWC fp16
// ---------------------------------------------------------------------------
__global__ void __launch_bounds__(256) transpose_ndhwc_h(const float* __restrict__ in,
                                                         __half* __restrict__ out) {
    __shared__ __half tile[32][66];
    const int n  = blockIdx.z;
    const int s0 = blockIdx.x * 32;
    const int c0 = blockIdx.y * 64;
    const int tx = threadIdx.x, ty = threadIdx.y;

    const float* ip = in  + (size_t)n * C_ * DHW;
    __half*      op = out + (size_t)n * DHW * C_;

#pragma unroll
    for (int i = 0; i < 64; i += 8)
        tile[tx][ty + i] = __float2half(ip[(size_t)(c0 + ty + i) * DHW + (s0 + tx)]);
    __syncthreads();
#pragma unroll
    for (int i = 0; i < 32; i += 8) {
        const int s = ty + i;
        __half2 v = *reinterpret_cast<const __half2*>(&tile[s][tx * 2]);
        *reinterpret_cast<__half2*>(&op[(size_t)(s0 + s) * C_ + c0 + tx * 2]) = v;
    }
}

// ---------------------------------------------------------------------------
// Per-axis separable taps
// ---------------------------------------------------------------------------
__device__ __forceinline__ void axis_taps(float c0, float c1, int size,
                                          int& base, float w[4]) {
    w[0] = w[1] = w[2] = w[3] = 0.0f;
    const float szf = (float)size;

    const bool v0 = (c0 >= -1.0f) && (c0 <= szf);
    float cc0 = fminf(fmaxf(c0, 0.0f), szf - 1.0f);
    const int lo0 = (int)floorf(cc0);
    const int hi0 = min(lo0 + 1, size - 1);
    const float f0 = cc0 - (float)lo0;

    const bool v1 = (c1 >= -1.0f) && (c1 <= szf);
    float cc1 = fminf(fmaxf(c1, 0.0f), szf - 1.0f);
    const int lo1 = (int)floorf(cc1);
    const int hi1 = min(lo1 + 1, size - 1);
    const float f1 = cc1 - (float)lo1;

    base = lo0;
    if (v0) { w[0]         += 1.0f - f0; w[hi0 - lo0] += f0; }
    if (v1) { w[lo1 - lo0] += 1.0f - f1; w[hi1 - lo0] += f1; }
}

__device__ __forceinline__ float sel4(int i, float a, float b, float c, float d) {
    return (i == 0) ? a : ((i == 1) ? b : ((i == 2) ? c : d));
}
__device__ __forceinline__ int sel4i(int i, int a, int b, int c, int d) {
    return (i == 0) ? a : ((i == 1) ? b : ((i == 2) ? c : d));
}

// ---------------------------------------------------------------------------
// Gather: grid (R, PH), block (32, PD). Warp = (pd, ph) pair, loops pw=0..6.
// z/y taps + per-lane zy combo weights/offsets hoisted out of the pw loop;
// per-pw work = x-taps + tiny ballot compaction + branch-free gather.
// Lane combo decomposition: combo = zi*16 + yi*4 + xi; lane -> {lane, lane+32}.
// combo+32 flips only z bit 1 => same yi/xi, ziB = ziA + 2.
// ---------------------------------------------------------------------------
__global__ void __launch_bounds__(32 * PD) roi3d_gather(const float* __restrict__ rois,
                                                        const uint2* __restrict__ fp,
                                                        float* __restrict__ out) {
    __shared__ int2 taps[PD][TAPCAP];

    const int r    = blockIdx.x;
    const int ph   = blockIdx.y;
    const int pd   = threadIdx.y;          // warp id
    const int lane = threadIdx.x;

    const float* roi = rois + r * 7;
    const int   b  = (int)__ldg(roi);
    const float x1 = __ldg(roi + 1) * 0.25f, y1 = __ldg(roi + 2) * 0.25f;
    const float z1 = __ldg(roi + 3) * 0.25f;
    const float x2 = __ldg(roi + 4) * 0.25f, y2 = __ldg(roi + 5) * 0.25f;
    const float z2 = __ldg(roi + 6) * 0.25f;
    const float sz = fmaxf(z2 - z1, 1.0f) * (1.0f / (PD * 2));
    const float sy = fmaxf(y2 - y1, 1.0f) * (1.0f / (PH * 2));
    const float sx = fmaxf(x2 - x1, 1.0f) * (1.0f / (PW * 2));
    const int bbase = b * DHW;

    // ---- per-warp z and y taps (fixed across pw) ----
    const float zc0 = z1 + ((float)(pd * 2) + 0.5f) * sz;
    const float yc0 = y1 + ((float)(ph * 2) + 0.5f) * sy;

    int bz, by;
    float wz[4], wy[4];
    axis_taps(zc0, zc0 + sz, D_, bz, wz);
    axis_taps(yc0, yc0 + sy, H_, by, wy);
    wz[0] *= 0.125f; wz[1] *= 0.125f; wz[2] *= 0.125f; wz[3] *= 0.125f;

    // uniform offsets (uint2 units: voxel * 32)
    const int zo0 = (bbase + bz * HW_) * 32;
    const int yo0 = by * W_ * 32;

    // ---- per-lane hoisted zy combo weights/offsets ----
    const int zyi = lane >> 2;             // 0..7
    const int ziA = zyi >> 2;              // 0..1   (ziB = ziA + 2)
    const int yiA = zyi & 3;
    const int xi  = lane & 3;

    const float wyA  = sel4(yiA, wy[0], wy[1], wy[2], wy[3]);
    const int   oyA  = yo0 + yiA * (W_ * 32);
    const float wzyA = sel4(ziA,     wz[0], wz[1], wz[2], wz[3]) * wyA;
    const float wzyB = sel4(ziA + 2, wz[0], wz[1], wz[2], wz[3]) * wyA;
    const int   ozyA = zo0 + ziA * (HW_ * 32) + oyA;
    const int   ozyB = ozyA + 2 * (HW_ * 32);

    int2* wlist = taps[pd];
    const uint2* __restrict__ fpl = fp + lane;   // lane = c4 channel group
    const int obase = ((r * C_ + lane * 4) * PD + pd) * NCELL + ph * PW;

    for (int pw = 0; pw < PW; pw++) {
        // ---- per-pw x taps ----
        const float xc0 = x1 + ((float)(pw * 2) + 0.5f) * sx;
        int bx;
        float wx[4];
        axis_taps(xc0, xc0 + sx, W_, bx, wx);
        const float wxv = sel4(xi, wx[0], wx[1], wx[2], wx[3]);
        const int   xb  = (bx + xi) * 32;

        __syncwarp();   // previous iteration's tap reads complete before overwrite

        // ---- cooperative compaction: 64 combos over 32 lanes x 2 ----
        const float w0 = wzyA * wxv;
        const int   o0 = ozyA + xb;
        unsigned bal = __ballot_sync(0xffffffffu, w0 != 0.0f);
        int nt = __popc(bal);
        if (w0 != 0.0f) {
            int slot = __popc(bal & ((1u << lane) - 1u));
            wlist[slot] = make_int2(o0, __float_as_int(w0));
        }

        const float w1 = wzyB * wxv;
        const int   o1 = ozyB + xb;
        unsigned bal1 = __ballot_sync(0xffffffffu, w1 != 0.0f);
        if (w1 != 0.0f) {
            int slot = nt + __popc(bal1 & ((1u << lane) - 1u));
            wlist[slot] = make_int2(o1, __float_as_int(w1));
        }
        nt += __popc(bal1);

        if (lane < 3) wlist[nt + lane] = make_int2(0, 0);   // pad
        const int nt4 = (nt + 3) & ~3;
        __syncwarp();

        // ---- branch-free gather ----
        float4 acc = make_float4(0.0f, 0.0f, 0.0f, 0.0f);
        for (int j = 0; j < nt4; j += 4) {
            const int4 p0 = *reinterpret_cast<const int4*>(&wlist[j]);
            const int4 p1 = *reinterpret_cast<const int4*>(&wlist[j + 2]);
            const uint2 v0 = __ldg(fpl + p0.x);
            const uint2 v1 = __ldg(fpl + p0.z);
            const uint2 v2 = __ldg(fpl + p1.x);
            const uint2 v3 = __ldg(fpl + p1.z);
            const float a0 = __int_as_float(p0.y);
            const float a1 = __int_as_float(p0.w);
            const float a2 = __int_as_float(p1.y);
            const float a3 = __int_as_float(p1.w);

            float2 f;
            f = __half22float2(*reinterpret_cast<const __half2*>(&v0.x));
            acc.x += f.x * a0; acc.y += f.y * a0;
            f = __half22float2(*reinterpret_cast<const __half2*>(&v0.y));
            acc.z += f.x * a0; acc.w += f.y * a0;
            f = __half22float2(*reinterpret_cast<const __half2*>(&v1.x));
            acc.x += f.x * a1; acc.y += f.y * a1;
            f = __half22float2(*reinterpret_cast<const __half2*>(&v1.y));
            acc.z += f.x * a1; acc.w += f.y * a1;
            f = __half22float2(*reinterpret_cast<const __half2*>(&v2.x));
            acc.x += f.x * a2; acc.y += f.y * a2;
            f = __half22float2(*reinterpret_cast<const __half2*>(&v2.y));
            acc.z += f.x * a2; acc.w += f.y * a2;
            f = __half22float2(*reinterpret_cast<const __half2*>(&v3.x));
            acc.x += f.x * a3; acc.y += f.y * a3;
            f = __half22float2(*reinterpret_cast<const __half2*>(&v3.y));
            acc.z += f.x * a3; acc.w += f.y * a3;
        }

        // ---- stores: out[r][c][pd][ph][pw], c = lane*4 ----
        const int ob = obase + pw;
        out[ob]                  = acc.x;
        out[ob + PD * NCELL]     = acc.y;
        out[ob + 2 * PD * NCELL] = acc.z;
        out[ob + 3 * PD * NCELL] = acc.w;
    }
}

// ---------------------------------------------------------------------------
extern "C" void kernel_launch(void* const* d_in, const int* in_sizes, int n_in,
                              void* d_out, int out_size) {
    const float* features = (const float*)d_in[0];
    const float* rois     = (const float*)d_in[1];
    float*       out      = (float*)d_out;

    __half* feat_t = nullptr;
    cudaGetSymbolAddress((void**)&feat_t, g_feat_t);

    // 1) NCDHW fp32 -> NDHWC fp16
    dim3 tg(DHW / 32, C_ / 64, N_);
    dim3 tb(32, 8);
    transpose_ndhwc_h<<<tg, tb>>>(features, feat_t);

    // 2) Gather: warp = (pd, ph), loops pw
    dim3 rg(R_, PH);
    dim3 rb(32, PD);
    roi3d_gather<<<rg, rb>>>(rois, (const uint2*)feat_t, out);
}

// round 12
// speedup vs baseline: 1.4083x; 1.4083x over previous
#include <cuda_runtime.h>
#include <cuda_fp16.h>
#include <cstdint>

#define N_  2
#define C_  128
#define D_  32
#define H_  64
#define W_  64
#define R_  256
#define PD  4
#define PH  7
#define PW  7
#define HW_ (H_ * W_)
#define DHW (D_ * H_ * W_)
#define NCELL (PH * PW)           // 49
#define NTASK (R_ * NCELL * PD)   // 50176
#define TAPCAP 68                 // 64 + pad

// Static scratch
__device__ __half g_feat_t[(size_t)N_ * DHW * C_];   // 64 MB NDHWC fp16 features
__device__ float  g_out_t[(size_t)NTASK * C_];       // 25.7 MB task-major output

// ---------------------------------------------------------------------------
// Transpose NCDHW fp32 -> NDHWC fp16
// ---------------------------------------------------------------------------
__global__ void __launch_bounds__(256) transpose_ndhwc_h(const float* __restrict__ in,
                                                         __half* __restrict__ out) {
    __shared__ __half tile[32][66];
    const int n  = blockIdx.z;
    const int s0 = blockIdx.x * 32;
    const int c0 = blockIdx.y * 64;
    const int tx = threadIdx.x, ty = threadIdx.y;

    const float* ip = in  + (size_t)n * C_ * DHW;
    __half*      op = out + (size_t)n * DHW * C_;

#pragma unroll
    for (int i = 0; i < 64; i += 8)
        tile[tx][ty + i] = __float2half(ip[(size_t)(c0 + ty + i) * DHW + (s0 + tx)]);
    __syncthreads();
#pragma unroll
    for (int i = 0; i < 32; i += 8) {
        const int s = ty + i;
        __half2 v = *reinterpret_cast<const __half2*>(&tile[s][tx * 2]);
        *reinterpret_cast<__half2*>(&op[(size_t)(s0 + s) * C_ + c0 + tx * 2]) = v;
    }
}

// ---------------------------------------------------------------------------
// Per-axis separable taps
// ---------------------------------------------------------------------------
__device__ __forceinline__ void axis_taps(float c0, float c1, int size,
                                          int& base, float w[4]) {
    w[0] = w[1] = w[2] = w[3] = 0.0f;
    const float szf = (float)size;

    const bool v0 = (c0 >= -1.0f) && (c0 <= szf);
    float cc0 = fminf(fmaxf(c0, 0.0f), szf - 1.0f);
    const int lo0 = (int)floorf(cc0);
    const int hi0 = min(lo0 + 1, size - 1);
    const float f0 = cc0 - (float)lo0;

    const bool v1 = (c1 >= -1.0f) && (c1 <= szf);
    float cc1 = fminf(fmaxf(c1, 0.0f), szf - 1.0f);
    const int lo1 = (int)floorf(cc1);
    const int hi1 = min(lo1 + 1, size - 1);
    const float f1 = cc1 - (float)lo1;

    base = lo0;
    if (v0) { w[0]         += 1.0f - f0; w[hi0 - lo0] += f0; }
    if (v1) { w[lo1 - lo0] += 1.0f - f1; w[hi1 - lo0] += f1; }
}

__device__ __forceinline__ float sel4(int i, float a, float b, float c, float d) {
    return (i == 0) ? a : ((i == 1) ? b : ((i == 2) ? c : d));
}
__device__ __forceinline__ int sel4i(int i, int a, int b, int c, int d) {
    return (i == 0) ? a : ((i == 1) ? b : ((i == 2) ? c : d));
}

// ---------------------------------------------------------------------------
// Gather: grid (R, NCELL), block (32, PD). Warp = one (cell, pd) task.
// (R9 structure — proven 67us @ issue 75.8%.)
// Change vs R9: output goes to task-major scratch via ONE coalesced
// STG.128 per lane instead of 4 scattered STG.32 (128 -> 4 store wavefronts).
// ---------------------------------------------------------------------------
__global__ void __launch_bounds__(32 * PD) roi3d_gather(const float* __restrict__ rois,
                                                        const uint2* __restrict__ fp,
                                                        float4* __restrict__ out_t) {
    __shared__ int2 taps[PD][TAPCAP];

    const int r    = blockIdx.x;
    const int cell = blockIdx.y;
    const int ph   = cell / PW;
    const int pw   = cell - ph * PW;
    const int pd   = threadIdx.y;          // warp id = pd
    const int lane = threadIdx.x;

    const float* roi = rois + r * 7;
    const int   b  = (int)__ldg(roi);
    const float x1 = __ldg(roi + 1) * 0.25f, y1 = __ldg(roi + 2) * 0.25f;
    const float z1 = __ldg(roi + 3) * 0.25f;
    const float x2 = __ldg(roi + 4) * 0.25f, y2 = __ldg(roi + 5) * 0.25f;
    const float z2 = __ldg(roi + 6) * 0.25f;
    const float sz = fmaxf(z2 - z1, 1.0f) * (1.0f / (PD * 2));
    const float sy = fmaxf(y2 - y1, 1.0f) * (1.0f / (PH * 2));
    const float sx = fmaxf(x2 - x1, 1.0f) * (1.0f / (PW * 2));
    const int bbase = b * DHW;

    const float zc0 = z1 + ((float)(pd * 2) + 0.5f) * sz;
    const float yc0 = y1 + ((float)(ph * 2) + 0.5f) * sy;
    const float xc0 = x1 + ((float)(pw * 2) + 0.5f) * sx;

    int bz, by, bx;
    float wz[4], wy[4], wx[4];
    axis_taps(zc0, zc0 + sz, D_, bz, wz);
    axis_taps(yc0, yc0 + sy, H_, by, wy);
    axis_taps(xc0, xc0 + sx, W_, bx, wx);
    wz[0] *= 0.125f; wz[1] *= 0.125f; wz[2] *= 0.125f; wz[3] *= 0.125f;

    // lane's combo decomposition: combo = zi*16 + yi*4 + xi; lane -> combos lane, lane+32
    const int zi0 = lane >> 4,       zi1 = (lane + 32) >> 4;
    const int yi0 = (lane >> 2) & 3;
    const int xi  = lane & 3;

    // uniform per-slot offsets (uint2 units: voxel * 32)
    const int zo0 = (bbase + bz * HW_) * 32;
    const int zo1 = zo0 + HW_ * 32, zo2 = zo0 + 2 * HW_ * 32, zo3 = zo0 + 3 * HW_ * 32;
    const int yo0 = by * W_ * 32;
    const int yo1 = yo0 + W_ * 32, yo2 = yo0 + 2 * W_ * 32, yo3 = yo0 + 3 * W_ * 32;
    const int xb  = bx * 32 + xi * 32;

    int2* wlist = taps[pd];

    // ---- cooperative compaction: 64 combos over 32 lanes x 2 ----
    int nt = 0;
    {
        const float wyx = sel4(yi0, wy[0], wy[1], wy[2], wy[3]) * wx[xi];
        const int   oyx = sel4i(yi0, yo0, yo1, yo2, yo3) + xb;

        const float w0 = sel4(zi0, wz[0], wz[1], wz[2], wz[3]) * wyx;
        const int   o0 = sel4i(zi0, zo0, zo1, zo2, zo3) + oyx;
        unsigned bal = __ballot_sync(0xffffffffu, w0 != 0.0f);
        if (w0 != 0.0f) {
            int slot = __popc(bal & ((1u << lane) - 1u));
            wlist[slot] = make_int2(o0, __float_as_int(w0));
        }
        nt = __popc(bal);

        const float w1 = sel4(zi1, wz[0], wz[1], wz[2], wz[3]) * wyx;
        const int   o1 = sel4i(zi1, zo0, zo1, zo2, zo3) + oyx;
        unsigned bal1 = __ballot_sync(0xffffffffu, w1 != 0.0f);
        if (w1 != 0.0f) {
            int slot = nt + __popc(bal1 & ((1u << lane) - 1u));
            wlist[slot] = make_int2(o1, __float_as_int(w1));
        }
        nt += __popc(bal1);
    }
    if (lane < 3) wlist[nt + lane] = make_int2(0, 0);   // pad
    const int nt4 = (nt + 3) & ~3;
    __syncwarp();

    // ---- branch-free gather (lane = channel group) ----
    const uint2* __restrict__ fpl = fp + lane;
    float4 acc = make_float4(0.0f, 0.0f, 0.0f, 0.0f);

    for (int j = 0; j < nt4; j += 4) {
        const int4 p0 = *reinterpret_cast<const int4*>(&wlist[j]);
        const int4 p1 = *reinterpret_cast<const int4*>(&wlist[j + 2]);
        const uint2 v0 = __ldg(fpl + p0.x);
        const uint2 v1 = __ldg(fpl + p0.z);
        const uint2 v2 = __ldg(fpl + p1.x);
        const uint2 v3 = __ldg(fpl + p1.z);
        const float a0 = __int_as_float(p0.y);
        const float a1 = __int_as_float(p0.w);
        const float a2 = __int_as_float(p1.y);
        const float a3 = __int_as_float(p1.w);

        float2 f;
        f = __half22float2(*reinterpret_cast<const __half2*>(&v0.x));
        acc.x += f.x * a0; acc.y += f.y * a0;
        f = __half22float2(*reinterpret_cast<const __half2*>(&v0.y));
        acc.z += f.x * a0; acc.w += f.y * a0;
        f = __half22float2(*reinterpret_cast<const __half2*>(&v1.x));
        acc.x += f.x * a1; acc.y += f.y * a1;
        f = __half22float2(*reinterpret_cast<const __half2*>(&v1.y));
        acc.z += f.x * a1; acc.w += f.y * a1;
        f = __half22float2(*reinterpret_cast<const __half2*>(&v2.x));
        acc.x += f.x * a2; acc.y += f.y * a2;
        f = __half22float2(*reinterpret_cast<const __half2*>(&v2.y));
        acc.z += f.x * a2; acc.w += f.y * a2;
        f = __half22float2(*reinterpret_cast<const __half2*>(&v3.x));
        acc.x += f.x * a3; acc.y += f.y * a3;
        f = __half22float2(*reinterpret_cast<const __half2*>(&v3.y));
        acc.z += f.x * a3; acc.w += f.y * a3;
    }

    // ---- coalesced store: out_t[task][c], task column = pd*NCELL + cell ----
    const int task = (r * PD + pd) * NCELL + cell;   // any unique mapping works
    out_t[task * (C_ / 4) + lane] = acc;
}

// ---------------------------------------------------------------------------
// Output transpose: out_t[r][pd*NCELL+cell][c] -> out[r][c][pd*NCELL+cell]
// Per roi: 196 x 128 transpose. Reads are L2-hot (buffer just written).
// ---------------------------------------------------------------------------
__global__ void __launch_bounds__(256) transpose_out(const float* __restrict__ in,
                                                     float* __restrict__ out) {
    __shared__ float tile[32][33];
    const int r  = blockIdx.z;
    const int t0 = blockIdx.x * 32;       // task-column tile origin (0..6*32)
    const int c0 = blockIdx.y * 32;       // channel tile origin
    const int tx = threadIdx.x, ty = threadIdx.y;

    const float* ir = in  + (size_t)r * (PD * NCELL) * C_;
    float*       orr = out + (size_t)r * C_ * (PD * NCELL);

#pragma unroll
    for (int i = 0; i < 32; i += 8) {
        const int t = t0 + ty + i;
        tile[ty + i][tx] = (t < PD * NCELL) ? ir[t * C_ + c0 + tx] : 0.0f;
    }
    __syncthreads();
#pragma unroll
    for (int i = 0; i < 32; i += 8) {
        const int c = c0 + ty + i;
        const int t = t0 + tx;
        if (t < PD * NCELL)
            orr[c * (PD * NCELL) + t] = tile[tx][ty + i];
    }
}

// ---------------------------------------------------------------------------
extern "C" void kernel_launch(void* const* d_in, const int* in_sizes, int n_in,
                              void* d_out, int out_size) {
    const float* features = (const float*)d_in[0];
    const float* rois     = (const float*)d_in[1];
    float*       out      = (float*)d_out;

    __half* feat_t = nullptr;
    cudaGetSymbolAddress((void**)&feat_t, g_feat_t);
    float* out_t = nullptr;
    cudaGetSymbolAddress((void**)&out_t, g_out_t);

    // 1) NCDHW fp32 -> NDHWC fp16
    dim3 tg(DHW / 32, C_ / 64, N_);
    dim3 tb(32, 8);
    transpose_ndhwc_h<<<tg, tb>>>(features, feat_t);

    // 2) Gather: warp per (cell, pd) task, coalesced task-major stores
    dim3 rg(R_, NCELL);
    dim3 rb(32, PD);
    roi3d_gather<<<rg, rb>>>(rois, (const uint2*)feat_t, (float4*)out_t);

    // 3) Output transpose to [r][c][pd][ph][pw]
    dim3 og((PD * NCELL + 31) / 32, C_ / 32, R_);
    dim3 ob(32, 8);
    transpose_out<<<og, ob>>>(out_t, out);
}

// round 13
// speedup vs baseline: 1.5205x; 1.0797x over previous
#include <cuda_runtime.h>
#include <cuda_fp16.h>
#include <cstdint>

#define N_  2
#define C_  128
#define D_  32
#define H_  64
#define W_  64
#define R_  256
#define PD  4
#define PH  7
#define PW  7
#define HW_ (H_ * W_)
#define DHW (D_ * H_ * W_)
#define NCELL (PH * PW)           // 49
#define TAPCAP 68                 // 64 + pad

// 64 MB static scratch: NDHWC features quantized to fp16
__device__ __half g_feat_t[(size_t)N_ * DHW * C_];

// ---------------------------------------------------------------------------
// Transpose NCDHW fp32 -> NDHWC fp16
//   64-spatial x 64-channel tiles, float2 loads (halved LDG count).
// ---------------------------------------------------------------------------
__global__ void __launch_bounds__(256) transpose_ndhwc_h(const float* __restrict__ in,
                                                         __half* __restrict__ out) {
    __shared__ __half tile[64][66];
    const int n  = blockIdx.z;
    const int s0 = blockIdx.x * 64;   // spatial tile origin
    const int c0 = blockIdx.y * 64;   // channel tile origin
    const int tx = threadIdx.x, ty = threadIdx.y;

    const float* ip = in  + (size_t)n * C_ * DHW;
    __half*      op = out + (size_t)n * DHW * C_;

    // load: channel row c0+ty+i, lane tx covers spatial pair s0+2tx, s0+2tx+1
#pragma unroll
    for (int i = 0; i < 64; i += 8) {
        const float2 v = *reinterpret_cast<const float2*>(
            &ip[(size_t)(c0 + ty + i) * DHW + s0 + 2 * tx]);
        tile[2 * tx][ty + i]     = __float2half(v.x);
        tile[2 * tx + 1][ty + i] = __float2half(v.y);
    }
    __syncthreads();

    // store: warp per spatial row, lane writes half2 (2 channels) — conflict-free
#pragma unroll
    for (int i = 0; i < 64; i += 8) {
        const int s = ty + i;
        __half2 v = *reinterpret_cast<const __half2*>(&tile[s][tx * 2]);
        *reinterpret_cast<__half2*>(&op[(size_t)(s0 + s) * C_ + c0 + tx * 2]) = v;
    }
}

// ---------------------------------------------------------------------------
// Per-axis separable taps
// ---------------------------------------------------------------------------
__device__ __forceinline__ void axis_taps(float c0, float c1, int size,
                                          int& base, float w[4]) {
    w[0] = w[1] = w[2] = w[3] = 0.0f;
    const float szf = (float)size;

    const bool v0 = (c0 >= -1.0f) && (c0 <= szf);
    float cc0 = fminf(fmaxf(c0, 0.0f), szf - 1.0f);
    const int lo0 = (int)floorf(cc0);
    const int hi0 = min(lo0 + 1, size - 1);
    const float f0 = cc0 - (float)lo0;

    const bool v1 = (c1 >= -1.0f) && (c1 <= szf);
    float cc1 = fminf(fmaxf(c1, 0.0f), szf - 1.0f);
    const int lo1 = (int)floorf(cc1);
    const int hi1 = min(lo1 + 1, size - 1);
    const float f1 = cc1 - (float)lo1;

    base = lo0;
    if (v0) { w[0]         += 1.0f - f0; w[hi0 - lo0] += f0; }
    if (v1) { w[lo1 - lo0] += 1.0f - f1; w[hi1 - lo0] += f1; }
}

__device__ __forceinline__ float sel4(int i, float a, float b, float c, float d) {
    return (i == 0) ? a : ((i == 1) ? b : ((i == 2) ? c : d));
}

// ---------------------------------------------------------------------------
// Gather: grid (R, NCELL), block (32, PD). Warp = one (cell, pd) task.
// (Proven R9 structure.) Offset math via IMAD from lane bits instead of
// SEL chains; z-weight selects reduced to single FSELs.
// Lane combos: combo = zi*16 + yi*4 + xi; lane -> {lane, lane+32};
// combo+32 flips z bit1 only => ziB = ziA + 2, same yi/xi.
// ---------------------------------------------------------------------------
__global__ void __launch_bounds__(32 * PD) roi3d_gather(const float* __restrict__ rois,
                                                        const uint2* __restrict__ fp,
                                                        float* __restrict__ out) {
    __shared__ int2 taps[PD][TAPCAP];

    const int r    = blockIdx.x;
    const int cell = blockIdx.y;
    const int ph   = cell / PW;
    const int pw   = cell - ph * PW;
    const int pd   = threadIdx.y;          // warp id = pd
    const int lane = threadIdx.x;

    const float* roi = rois + r * 7;
    const int   b  = (int)__ldg(roi);
    const float x1 = __ldg(roi + 1) * 0.25f, y1 = __ldg(roi + 2) * 0.25f;
    const float z1 = __ldg(roi + 3) * 0.25f;
    const float x2 = __ldg(roi + 4) * 0.25f, y2 = __ldg(roi + 5) * 0.25f;
    const float z2 = __ldg(roi + 6) * 0.25f;
    const float sz = fmaxf(z2 - z1, 1.0f) * (1.0f / (PD * 2));
    const float sy = fmaxf(y2 - y1, 1.0f) * (1.0f / (PH * 2));
    const float sx = fmaxf(x2 - x1, 1.0f) * (1.0f / (PW * 2));
    const int bbase = b * DHW;

    const float zc0 = z1 + ((float)(pd * 2) + 0.5f) * sz;
    const float yc0 = y1 + ((float)(ph * 2) + 0.5f) * sy;
    const float xc0 = x1 + ((float)(pw * 2) + 0.5f) * sx;

    int bz, by, bx;
    float wz[4], wy[4], wx[4];
    axis_taps(zc0, zc0 + sz, D_, bz, wz);
    axis_taps(yc0, yc0 + sy, H_, by, wy);
    axis_taps(xc0, xc0 + sx, W_, bx, wx);
    wz[0] *= 0.125f; wz[1] *= 0.125f; wz[2] *= 0.125f; wz[3] *= 0.125f;

    // lane's combo decomposition
    const int zi0 = lane >> 4;             // 0..1 (combo B: zi0 + 2)
    const int yi0 = (lane >> 2) & 3;
    const int xi  = lane & 3;

    // direct IMAD offsets (uint2 units: voxel * 32)
    const int HW32 = HW_ * 32;
    const int W32  = W_ * 32;
    const int oyx = yi0 * W32 + (bx + xi) * 32 + by * W32 * 0 /* by folded below */;
    const int o0  = (bbase + bz * HW_) * 32 + zi0 * HW32 + by * W32 + oyx;
    const int o1  = o0 + 2 * HW32;

    int2* wlist = taps[pd];

    // ---- cooperative compaction: 64 combos over 32 lanes x 2 ----
    int nt = 0;
    {
        const float wyx = sel4(yi0, wy[0], wy[1], wy[2], wy[3]) * wx[xi];

        const float w0 = (zi0 == 0 ? wz[0] : wz[1]) * wyx;
        unsigned bal = __ballot_sync(0xffffffffu, w0 != 0.0f);
        if (w0 != 0.0f) {
            int slot = __popc(bal & ((1u << lane) - 1u));
            wlist[slot] = make_int2(o0, __float_as_int(w0));
        }
        nt = __popc(bal);

        const float w1 = (zi0 == 0 ? wz[2] : wz[3]) * wyx;
        unsigned bal1 = __ballot_sync(0xffffffffu, w1 != 0.0f);
        if (w1 != 0.0f) {
            int slot = nt + __popc(bal1 & ((1u << lane) - 1u));
            wlist[slot] = make_int2(o1, __float_as_int(w1));
        }
        nt += __popc(bal1);
    }
    if (lane < 3) wlist[nt + lane] = make_int2(0, 0);   // pad
    const int nt4 = (nt + 3) & ~3;
    __syncwarp();

    // ---- branch-free gather (lane = channel group) ----
    const uint2* __restrict__ fpl = fp + lane;
    float4 acc = make_float4(0.0f, 0.0f, 0.0f, 0.0f);

    for (int j = 0; j < nt4; j += 4) {
        const int4 p0 = *reinterpret_cast<const int4*>(&wlist[j]);
        const int4 p1 = *reinterpret_cast<const int4*>(&wlist[j + 2]);
        const uint2 v0 = __ldg(fpl + p0.x);
        const uint2 v1 = __ldg(fpl + p0.z);
        const uint2 v2 = __ldg(fpl + p1.x);
        const uint2 v3 = __ldg(fpl + p1.z);
        const float a0 = __int_as_float(p0.y);
        const float a1 = __int_as_float(p0.w);
        const float a2 = __int_as_float(p1.y);
        const float a3 = __int_as_float(p1.w);

        float2 f;
        f = __half22float2(*reinterpret_cast<const __half2*>(&v0.x));
        acc.x += f.x * a0; acc.y += f.y * a0;
        f = __half22float2(*reinterpret_cast<const __half2*>(&v0.y));
        acc.z += f.x * a0; acc.w += f.y * a0;
        f = __half22float2(*reinterpret_cast<const __half2*>(&v1.x));
        acc.x += f.x * a1; acc.y += f.y * a1;
        f = __half22float2(*reinterpret_cast<const __half2*>(&v1.y));
        acc.z += f.x * a1; acc.w += f.y * a1;
        f = __half22float2(*reinterpret_cast<const __half2*>(&v2.x));
        acc.x += f.x * a2; acc.y += f.y * a2;
        f = __half22float2(*reinterpret_cast<const __half2*>(&v2.y));
        acc.z += f.x * a2; acc.w += f.y * a2;
        f = __half22float2(*reinterpret_cast<const __half2*>(&v3.x));
        acc.x += f.x * a3; acc.y += f.y * a3;
        f = __half22float2(*reinterpret_cast<const __half2*>(&v3.y));
        acc.z += f.x * a3; acc.w += f.y * a3;
    }

    // ---- direct stores: out[r][c][pd][ph][pw], c = lane*4 ----
    const int ob = ((r * C_ + lane * 4) * PD + pd) * NCELL + cell;
    out[ob]                  = acc.x;
    out[ob + PD * NCELL]     = acc.y;
    out[ob + 2 * PD * NCELL] = acc.z;
    out[ob + 3 * PD * NCELL] = acc.w;
}

// ---------------------------------------------------------------------------
extern "C" void kernel_launch(void* const* d_in, const int* in_sizes, int n_in,
                              void* d_out, int out_size) {
    const float* features = (const float*)d_in[0];
    const float* rois     = (const float*)d_in[1];
    float*       out      = (float*)d_out;

    __half* feat_t = nullptr;
    cudaGetSymbolAddress((void**)&feat_t, g_feat_t);

    // 1) NCDHW fp32 -> NDHWC fp16 (float2 loads, 64x64 tiles)
    dim3 tg(DHW / 64, C_ / 64, N_);
    dim3 tb(32, 8);
    transpose_ndhwc_h<<<tg, tb>>>(features, feat_t);

    // 2) Gather: warp per (cell, pd) task
    dim3 rg(R_, NCELL);
    dim3 rb(32, PD);
    roi3d_gather<<<rg, rb>>>(rois, (const uint2*)feat_t, out);
}

// round 14
// speedup vs baseline: 1.5410x; 1.0135x over previous
#include <cuda_runtime.h>
#include <cuda_fp16.h>
#include <cstdint>

#define N_  2
#define C_  128
#define D_  32
#define H_  64
#define W_  64
#define R_  256
#define PD  4
#define PH  7
#define PW  7
#define HW_ (H_ * W_)
#define DHW (D_ * H_ * W_)
#define NCELL (PH * PW)           // 49
#define TAPCAP 72                 // 64 + pad to x4

// 64 MB static scratch: NDHWC features quantized to fp16
__device__ __half g_feat_t[(size_t)N_ * DHW * C_];

// ---------------------------------------------------------------------------
// Transpose NCDHW fp32 -> NDHWC fp16 (R12 version: 64x64 tiles, float2 loads)
// ---------------------------------------------------------------------------
__global__ void __launch_bounds__(256) transpose_ndhwc_h(const float* __restrict__ in,
                                                         __half* __restrict__ out) {
    __shared__ __half tile[64][66];
    const int n  = blockIdx.z;
    const int s0 = blockIdx.x * 64;
    const int c0 = blockIdx.y * 64;
    const int tx = threadIdx.x, ty = threadIdx.y;

    const float* ip = in  + (size_t)n * C_ * DHW;
    __half*      op = out + (size_t)n * DHW * C_;

#pragma unroll
    for (int i = 0; i < 64; i += 8) {
        const float2 v = *reinterpret_cast<const float2*>(
            &ip[(size_t)(c0 + ty + i) * DHW + s0 + 2 * tx]);
        tile[2 * tx][ty + i]     = __float2half(v.x);
        tile[2 * tx + 1][ty + i] = __float2half(v.y);
    }
    __syncthreads();

#pragma unroll
    for (int i = 0; i < 64; i += 8) {
        const int s = ty + i;
        __half2 v = *reinterpret_cast<const __half2*>(&tile[s][tx * 2]);
        *reinterpret_cast<__half2*>(&op[(size_t)(s0 + s) * C_ + c0 + tx * 2]) = v;
    }
}

// ---------------------------------------------------------------------------
// Per-axis separable taps
// ---------------------------------------------------------------------------
__device__ __forceinline__ void axis_taps(float c0, float c1, int size,
                                          int& base, float w[4]) {
    w[0] = w[1] = w[2] = w[3] = 0.0f;
    const float szf = (float)size;

    const bool v0 = (c0 >= -1.0f) && (c0 <= szf);
    float cc0 = fminf(fmaxf(c0, 0.0f), szf - 1.0f);
    const int lo0 = (int)floorf(cc0);
    const int hi0 = min(lo0 + 1, size - 1);
    const float f0 = cc0 - (float)lo0;

    const bool v1 = (c1 >= -1.0f) && (c1 <= szf);
    float cc1 = fminf(fmaxf(c1, 0.0f), szf - 1.0f);
    const int lo1 = (int)floorf(cc1);
    const int hi1 = min(lo1 + 1, size - 1);
    const float f1 = cc1 - (float)lo1;

    base = lo0;
    if (v0) { w[0]         += 1.0f - f0; w[hi0 - lo0] += f0; }
    if (v1) { w[lo1 - lo0] += 1.0f - f1; w[hi1 - lo0] += f1; }
}

__device__ __forceinline__ float sel4(int i, float a, float b, float c, float d) {
    return (i == 0) ? a : ((i == 1) ? b : ((i == 2) ? c : d));
}

__device__ __forceinline__ __half2 h2_from_bits(int b) {
    __half2 h;
    *reinterpret_cast<int*>(&h) = b;
    return h;
}

// ---------------------------------------------------------------------------
// Gather: grid (R, NCELL), block (32, PD). Warp = one (cell, pd) task.
// R12 structure; tap weights stored as duplicated half2; inner loop does
// paired fp16 HMUL2/HFMA2 with fp32 flush per pair (halves F2F+FMA count).
// ---------------------------------------------------------------------------
__global__ void __launch_bounds__(32 * PD) roi3d_gather(const float* __restrict__ rois,
                                                        const uint2* __restrict__ fp,
                                                        float* __restrict__ out) {
    __shared__ int2 taps[PD][TAPCAP];

    const int r    = blockIdx.x;
    const int cell = blockIdx.y;
    const int ph   = cell / PW;
    const int pw   = cell - ph * PW;
    const int pd   = threadIdx.y;          // warp id = pd
    const int lane = threadIdx.x;

    const float* roi = rois + r * 7;
    const int   b  = (int)__ldg(roi);
    const float x1 = __ldg(roi + 1) * 0.25f, y1 = __ldg(roi + 2) * 0.25f;
    const float z1 = __ldg(roi + 3) * 0.25f;
    const float x2 = __ldg(roi + 4) * 0.25f, y2 = __ldg(roi + 5) * 0.25f;
    const float z2 = __ldg(roi + 6) * 0.25f;
    const float sz = fmaxf(z2 - z1, 1.0f) * (1.0f / (PD * 2));
    const float sy = fmaxf(y2 - y1, 1.0f) * (1.0f / (PH * 2));
    const float sx = fmaxf(x2 - x1, 1.0f) * (1.0f / (PW * 2));
    const int bbase = b * DHW;

    const float zc0 = z1 + ((float)(pd * 2) + 0.5f) * sz;
    const float yc0 = y1 + ((float)(ph * 2) + 0.5f) * sy;
    const float xc0 = x1 + ((float)(pw * 2) + 0.5f) * sx;

    int bz, by, bx;
    float wz[4], wy[4], wx[4];
    axis_taps(zc0, zc0 + sz, D_, bz, wz);
    axis_taps(yc0, yc0 + sy, H_, by, wy);
    axis_taps(xc0, xc0 + sx, W_, bx, wx);
    wz[0] *= 0.125f; wz[1] *= 0.125f; wz[2] *= 0.125f; wz[3] *= 0.125f;

    // lane's combo decomposition: combo = zi*16 + yi*4 + xi; lane -> {lane, lane+32}
    const int zi0 = lane >> 4;             // 0..1 (combo B: zi0 + 2)
    const int yi0 = (lane >> 2) & 3;
    const int xi  = lane & 3;

    // direct IMAD offsets (uint2 units: voxel * 32)
    const int HW32 = HW_ * 32;
    const int W32  = W_ * 32;
    const int o0 = (bbase + bz * HW_) * 32 + zi0 * HW32 + (by + yi0) * W32
                 + (bx + xi) * 32;
    const int o1 = o0 + 2 * HW32;

    int2* wlist = taps[pd];

    // ---- cooperative compaction (weights packed as duplicated half2) ----
    int nt = 0;
    {
        const float wyx = sel4(yi0, wy[0], wy[1], wy[2], wy[3]) * wx[xi];

        const float w0 = (zi0 == 0 ? wz[0] : wz[1]) * wyx;
        unsigned bal = __ballot_sync(0xffffffffu, w0 != 0.0f);
        if (w0 != 0.0f) {
            int slot = __popc(bal & ((1u << lane) - 1u));
            __half2 wh = __float2half2_rn(w0);
            wlist[slot] = make_int2(o0, *reinterpret_cast<int*>(&wh));
        }
        nt = __popc(bal);

        const float w1 = (zi0 == 0 ? wz[2] : wz[3]) * wyx;
        unsigned bal1 = __ballot_sync(0xffffffffu, w1 != 0.0f);
        if (w1 != 0.0f) {
            int slot = nt + __popc(bal1 & ((1u << lane) - 1u));
            __half2 wh = __float2half2_rn(w1);
            wlist[slot] = make_int2(o1, *reinterpret_cast<int*>(&wh));
        }
        nt += __popc(bal1);
    }
    if (lane < 3) wlist[nt + lane] = make_int2(0, 0);   // zero-weight pad
    const int nt4 = (nt + 3) & ~3;
    __syncwarp();

    // ---- branch-free gather: fp16 pair FMA, fp32 flush per pair ----
    const uint2* __restrict__ fpl = fp + lane;
    float4 acc = make_float4(0.0f, 0.0f, 0.0f, 0.0f);

    for (int j = 0; j < nt4; j += 4) {
        const int4 p0 = *reinterpret_cast<const int4*>(&wlist[j]);     // taps 0,1
        const int4 p1 = *reinterpret_cast<const int4*>(&wlist[j + 2]); // taps 2,3
        const uint2 v0 = __ldg(fpl + p0.x);
        const uint2 v1 = __ldg(fpl + p0.z);
        const uint2 v2 = __ldg(fpl + p1.x);
        const uint2 v3 = __ldg(fpl + p1.z);

        const __half2 w0 = h2_from_bits(p0.y);
        const __half2 w1 = h2_from_bits(p0.w);
        const __half2 w2 = h2_from_bits(p1.y);
        const __half2 w3 = h2_from_bits(p1.w);

        // pair A = taps 0,1
        __half2 hA01 = __hmul2(h2_from_bits((int)v0.x), w0);
        __half2 hA23 = __hmul2(h2_from_bits((int)v0.y), w0);
        hA01 = __hfma2(h2_from_bits((int)v1.x), w1, hA01);
        hA23 = __hfma2(h2_from_bits((int)v1.y), w1, hA23);

        // pair B = taps 2,3
        __half2 hB01 = __hmul2(h2_from_bits((int)v2.x), w2);
        __half2 hB23 = __hmul2(h2_from_bits((int)v2.y), w2);
        hB01 = __hfma2(h2_from_bits((int)v3.x), w3, hB01);
        hB23 = __hfma2(h2_from_bits((int)v3.y), w3, hB23);

        // flush pairs to fp32
        float2 f;
        f = __half22float2(hA01); acc.x += f.x; acc.y += f.y;
        f = __half22float2(hA23); acc.z += f.x; acc.w += f.y;
        f = __half22float2(hB01); acc.x += f.x; acc.y += f.y;
        f = __half22float2(hB23); acc.z += f.x; acc.w += f.y;
    }

    // ---- direct stores: out[r][c][pd][ph][pw], c = lane*4 ----
    const int ob = ((r * C_ + lane * 4) * PD + pd) * NCELL + cell;
    out[ob]                  = acc.x;
    out[ob + PD * NCELL]     = acc.y;
    out[ob + 2 * PD * NCELL] = acc.z;
    out[ob + 3 * PD * NCELL] = acc.w;
}

// ---------------------------------------------------------------------------
extern "C" void kernel_launch(void* const* d_in, const int* in_sizes, int n_in,
                              void* d_out, int out_size) {
    const float* features = (const float*)d_in[0];
    const float* rois     = (const float*)d_in[1];
    float*       out      = (float*)d_out;

    __half* feat_t = nullptr;
    cudaGetSymbolAddress((void**)&feat_t, g_feat_t);

    // 1) NCDHW fp32 -> NDHWC fp16
    dim3 tg(DHW / 64, C_ / 64, N_);
    dim3 tb(32, 8);
    transpose_ndhwc_h<<<tg, tb>>>(features, feat_t);

    // 2) Gather
    dim3 rg(R_, NCELL);
    dim3 rb(32, PD);
    roi3d_gather<<<rg, rb>>>(rois, (const uint2*)feat_t, out);
}

// round 15
// speedup vs baseline: 1.5528x; 1.0076x over previous
#include <cuda_runtime.h>
#include <cuda_fp16.h>
#include <cstdint>

#define N_  2
#define C_  128
#define D_  32
#define H_  64
#define W_  64
#define R_  256
#define PD  4
#define PH  7
#define PW  7
#define HW_ (H_ * W_)
#define DHW (D_ * H_ * W_)
#define NCELL (PH * PW)           // 49
#define TAPCAP 72                 // 64 + 7 pad (x8 rounding)

// 64 MB static scratch: NDHWC features quantized to fp16
__device__ __half g_feat_t[(size_t)N_ * DHW * C_];

// ---------------------------------------------------------------------------
// Transpose NCDHW fp32 -> NDHWC fp16 (64x64 tiles, float2 streaming loads)
// ---------------------------------------------------------------------------
__global__ void __launch_bounds__(256) transpose_ndhwc_h(const float* __restrict__ in,
                                                         __half* __restrict__ out) {
    __shared__ __half tile[64][66];
    const int n  = blockIdx.z;
    const int s0 = blockIdx.x * 64;
    const int c0 = blockIdx.y * 64;
    const int tx = threadIdx.x, ty = threadIdx.y;

    const float* ip = in  + (size_t)n * C_ * DHW;
    __half*      op = out + (size_t)n * DHW * C_;

#pragma unroll
    for (int i = 0; i < 64; i += 8) {
        // streaming read: fp32 source is never re-read; keep it out of L2
        const float2 v = __ldcs(reinterpret_cast<const float2*>(
            &ip[(size_t)(c0 + ty + i) * DHW + s0 + 2 * tx]));
        tile[2 * tx][ty + i]     = __float2half(v.x);
        tile[2 * tx + 1][ty + i] = __float2half(v.y);
    }
    __syncthreads();

#pragma unroll
    for (int i = 0; i < 64; i += 8) {
        const int s = ty + i;
        __half2 v = *reinterpret_cast<const __half2*>(&tile[s][tx * 2]);
        *reinterpret_cast<__half2*>(&op[(size_t)(s0 + s) * C_ + c0 + tx * 2]) = v;
    }
}

// ---------------------------------------------------------------------------
// Per-axis separable taps
// ---------------------------------------------------------------------------
__device__ __forceinline__ void axis_taps(float c0, float c1, int size,
                                          int& base, float w[4]) {
    w[0] = w[1] = w[2] = w[3] = 0.0f;
    const float szf = (float)size;

    const bool v0 = (c0 >= -1.0f) && (c0 <= szf);
    float cc0 = fminf(fmaxf(c0, 0.0f), szf - 1.0f);
    const int lo0 = (int)floorf(cc0);
    const int hi0 = min(lo0 + 1, size - 1);
    const float f0 = cc0 - (float)lo0;

    const bool v1 = (c1 >= -1.0f) && (c1 <= szf);
    float cc1 = fminf(fmaxf(c1, 0.0f), szf - 1.0f);
    const int lo1 = (int)floorf(cc1);
    const int hi1 = min(lo1 + 1, size - 1);
    const float f1 = cc1 - (float)lo1;

    base = lo0;
    if (v0) { w[0]         += 1.0f - f0; w[hi0 - lo0] += f0; }
    if (v1) { w[lo1 - lo0] += 1.0f - f1; w[hi1 - lo0] += f1; }
}

__device__ __forceinline__ float sel4(int i, float a, float b, float c, float d) {
    return (i == 0) ? a : ((i == 1) ? b : ((i == 2) ? c : d));
}

__device__ __forceinline__ __half2 h2_from_bits(int b) {
    __half2 h;
    *reinterpret_cast<int*>(&h) = b;
    return h;
}

// ---------------------------------------------------------------------------
// Gather: grid (R, NCELL), block (32, PD). Warp = one (cell, pd) task.
// fp16-pair FMA with fp32 flush; 8-tap unrolled loop for MLP=8.
// ---------------------------------------------------------------------------
__global__ void __launch_bounds__(32 * PD, 12) roi3d_gather(const float* __restrict__ rois,
                                                            const uint2* __restrict__ fp,
                                                            float* __restrict__ out) {
    __shared__ int2 taps[PD][TAPCAP];

    const int r    = blockIdx.x;
    const int cell = blockIdx.y;
    const int ph   = cell / PW;
    const int pw   = cell - ph * PW;
    const int pd   = threadIdx.y;          // warp id = pd
    const int lane = threadIdx.x;

    const float* roi = rois + r * 7;
    const int   b  = (int)__ldg(roi);
    const float x1 = __ldg(roi + 1) * 0.25f, y1 = __ldg(roi + 2) * 0.25f;
    const float z1 = __ldg(roi + 3) * 0.25f;
    const float x2 = __ldg(roi + 4) * 0.25f, y2 = __ldg(roi + 5) * 0.25f;
    const float z2 = __ldg(roi + 6) * 0.25f;
    const float sz = fmaxf(z2 - z1, 1.0f) * (1.0f / (PD * 2));
    const float sy = fmaxf(y2 - y1, 1.0f) * (1.0f / (PH * 2));
    const float sx = fmaxf(x2 - x1, 1.0f) * (1.0f / (PW * 2));
    const int bbase = b * DHW;

    const float zc0 = z1 + ((float)(pd * 2) + 0.5f) * sz;
    const float yc0 = y1 + ((float)(ph * 2) + 0.5f) * sy;
    const float xc0 = x1 + ((float)(pw * 2) + 0.5f) * sx;

    int bz, by, bx;
    float wz[4], wy[4], wx[4];
    axis_taps(zc0, zc0 + sz, D_, bz, wz);
    axis_taps(yc0, yc0 + sy, H_, by, wy);
    axis_taps(xc0, xc0 + sx, W_, bx, wx);
    wz[0] *= 0.125f; wz[1] *= 0.125f; wz[2] *= 0.125f; wz[3] *= 0.125f;

    // lane's combo decomposition: combo = zi*16 + yi*4 + xi; lane -> {lane, lane+32}
    const int zi0 = lane >> 4;             // 0..1 (combo B: zi0 + 2)
    const int yi0 = (lane >> 2) & 3;
    const int xi  = lane & 3;

    // direct IMAD offsets (uint2 units: voxel * 32)
    const int HW32 = HW_ * 32;
    const int W32  = W_ * 32;
    const int o0 = (bbase + bz * HW_) * 32 + zi0 * HW32 + (by + yi0) * W32
                 + (bx + xi) * 32;
    const int o1 = o0 + 2 * HW32;

    int2* wlist = taps[pd];

    // ---- cooperative compaction (weights packed as duplicated half2) ----
    int nt = 0;
    {
        const float wyx = sel4(yi0, wy[0], wy[1], wy[2], wy[3]) * wx[xi];

        const float w0 = (zi0 == 0 ? wz[0] : wz[1]) * wyx;
        unsigned bal = __ballot_sync(0xffffffffu, w0 != 0.0f);
        if (w0 != 0.0f) {
            int slot = __popc(bal & ((1u << lane) - 1u));
            __half2 wh = __float2half2_rn(w0);
            wlist[slot] = make_int2(o0, *reinterpret_cast<int*>(&wh));
        }
        nt = __popc(bal);

        const float w1 = (zi0 == 0 ? wz[2] : wz[3]) * wyx;
        unsigned bal1 = __ballot_sync(0xffffffffu, w1 != 0.0f);
        if (w1 != 0.0f) {
            int slot = nt + __popc(bal1 & ((1u << lane) - 1u));
            __half2 wh = __float2half2_rn(w1);
            wlist[slot] = make_int2(o1, *reinterpret_cast<int*>(&wh));
        }
        nt += __popc(bal1);
    }
    if (lane < 7) wlist[nt + lane] = make_int2(0, 0);   // zero-weight pad to x8
    const int nt8 = (nt + 7) & ~7;
    __syncwarp();

    // ---- branch-free gather: 8 taps per iter, fp16 pair FMA, fp32 flush ----
    const uint2* __restrict__ fpl = fp + lane;
    float4 acc = make_float4(0.0f, 0.0f, 0.0f, 0.0f);

    for (int j = 0; j < nt8; j += 8) {
        const int4 p0 = *reinterpret_cast<const int4*>(&wlist[j]);
        const int4 p1 = *reinterpret_cast<const int4*>(&wlist[j + 2]);
        const int4 p2 = *reinterpret_cast<const int4*>(&wlist[j + 4]);
        const int4 p3 = *reinterpret_cast<const int4*>(&wlist[j + 6]);
        // 8 independent loads in flight
        const uint2 v0 = __ldg(fpl + p0.x);
        const uint2 v1 = __ldg(fpl + p0.z);
        const uint2 v2 = __ldg(fpl + p1.x);
        const uint2 v3 = __ldg(fpl + p1.z);
        const uint2 v4 = __ldg(fpl + p2.x);
        const uint2 v5 = __ldg(fpl + p2.z);
        const uint2 v6 = __ldg(fpl + p3.x);
        const uint2 v7 = __ldg(fpl + p3.z);

        // pair A = taps 0,1
        __half2 h01 = __hmul2(h2_from_bits((int)v0.x), h2_from_bits(p0.y));
        __half2 h23 = __hmul2(h2_from_bits((int)v0.y), h2_from_bits(p0.y));
        h01 = __hfma2(h2_from_bits((int)v1.x), h2_from_bits(p0.w), h01);
        h23 = __hfma2(h2_from_bits((int)v1.y), h2_from_bits(p0.w), h23);
        float2 f;
        f = __half22float2(h01); acc.x += f.x; acc.y += f.y;
        f = __half22float2(h23); acc.z += f.x; acc.w += f.y;

        // pair B = taps 2,3
        h01 = __hmul2(h2_from_bits((int)v2.x), h2_from_bits(p1.y));
        h23 = __hmul2(h2_from_bits((int)v2.y), h2_from_bits(p1.y));
        h01 = __hfma2(h2_from_bits((int)v3.x), h2_from_bits(p1.w), h01);
        h23 = __hfma2(h2_from_bits((int)v3.y), h2_from_bits(p1.w), h23);
        f = __half22float2(h01); acc.x += f.x; acc.y += f.y;
        f = __half22float2(h23); acc.z += f.x; acc.w += f.y;

        // pair C = taps 4,5
        h01 = __hmul2(h2_from_bits((int)v4.x), h2_from_bits(p2.y));
        h23 = __hmul2(h2_from_bits((int)v4.y), h2_from_bits(p2.y));
        h01 = __hfma2(h2_from_bits((int)v5.x), h2_from_bits(p2.w), h01);
        h23 = __hfma2(h2_from_bits((int)v5.y), h2_from_bits(p2.w), h23);
        f = __half22float2(h01); acc.x += f.x; acc.y += f.y;
        f = __half22float2(h23); acc.z += f.x; acc.w += f.y;

        // pair D = taps 6,7
        h01 = __hmul2(h2_from_bits((int)v6.x), h2_from_bits(p3.y));
        h23 = __hmul2(h2_from_bits((int)v6.y), h2_from_bits(p3.y));
        h01 = __hfma2(h2_from_bits((int)v7.x), h2_from_bits(p3.w), h01);
        h23 = __hfma2(h2_from_bits((int)v7.y), h2_from_bits(p3.w), h23);
        f = __half22float2(h01); acc.x += f.x; acc.y += f.y;
        f = __half22float2(h23); acc.z += f.x; acc.w += f.y;
    }

    // ---- direct stores: out[r][c][pd][ph][pw], c = lane*4 ----
    const int ob = ((r * C_ + lane * 4) * PD + pd) * NCELL + cell;
    out[ob]                  = acc.x;
    out[ob + PD * NCELL]     = acc.y;
    out[ob + 2 * PD * NCELL] = acc.z;
    out[ob + 3 * PD * NCELL] = acc.w;
}

// ---------------------------------------------------------------------------
extern "C" void kernel_launch(void* const* d_in, const int* in_sizes, int n_in,
                              void* d_out, int out_size) {
    const float* features = (const float*)d_in[0];
    const float* rois     = (const float*)d_in[1];
    float*       out      = (float*)d_out;

    __half* feat_t = nullptr;
    cudaGetSymbolAddress((void**)&feat_t, g_feat_t);

    // 1) NCDHW fp32 -> NDHWC fp16
    dim3 tg(DHW / 64, C_ / 64, N_);
    dim3 tb(32, 8);
    transpose_ndhwc_h<<<tg, tb>>>(features, feat_t);

    // 2) Gather
    dim3 rg(R_, NCELL);
    dim3 rb(32, PD);
    roi3d_gather<<<rg, rb>>>(rois, (const uint2*)feat_t, out);
}

// round 16
// speedup vs baseline: 1.6487x; 1.0617x over previous
#include <cuda_runtime.h>
#include <cuda_fp16.h>
#include <cstdint>

#define N_  2
#define C_  128
#define D_  32
#define H_  64
#define W_  64
#define R_  256
#define PD  4
#define PH  7
#define PW  7
#define HW_ (H_ * W_)
#define DHW (D_ * H_ * W_)
#define NCELL (PH * PW)           // 49
#define TAPCAP 68                 // 64 + pad to x4

// 64 MB static scratch: NDHWC features quantized to fp16
__device__ __half g_feat_t[(size_t)N_ * DHW * C_];

// ---------------------------------------------------------------------------
// Transpose NCDHW fp32 -> NDHWC fp16 (64x64 tiles, float2 streaming loads)
// ---------------------------------------------------------------------------
__global__ void __launch_bounds__(256) transpose_ndhwc_h(const float* __restrict__ in,
                                                         __half* __restrict__ out) {
    __shared__ __half tile[64][66];
    const int n  = blockIdx.z;
    const int s0 = blockIdx.x * 64;
    const int c0 = blockIdx.y * 64;
    const int tx = threadIdx.x, ty = threadIdx.y;

    const float* ip = in  + (size_t)n * C_ * DHW;
    __half*      op = out + (size_t)n * DHW * C_;

#pragma unroll
    for (int i = 0; i < 64; i += 8) {
        const float2 v = __ldcs(reinterpret_cast<const float2*>(
            &ip[(size_t)(c0 + ty + i) * DHW + s0 + 2 * tx]));
        tile[2 * tx][ty + i]     = __float2half(v.x);
        tile[2 * tx + 1][ty + i] = __float2half(v.y);
    }
    __syncthreads();

#pragma unroll
    for (int i = 0; i < 64; i += 8) {
        const int s = ty + i;
        __half2 v = *reinterpret_cast<const __half2*>(&tile[s][tx * 2]);
        *reinterpret_cast<__half2*>(&op[(size_t)(s0 + s) * C_ + c0 + tx * 2]) = v;
    }
}

// ---------------------------------------------------------------------------
// Per-axis separable taps
// ---------------------------------------------------------------------------
__device__ __forceinline__ void axis_taps(float c0, float c1, int size,
                                          int& base, float w[4]) {
    w[0] = w[1] = w[2] = w[3] = 0.0f;
    const float szf = (float)size;

    const bool v0 = (c0 >= -1.0f) && (c0 <= szf);
    float cc0 = fminf(fmaxf(c0, 0.0f), szf - 1.0f);
    const int lo0 = (int)floorf(cc0);
    const int hi0 = min(lo0 + 1, size - 1);
    const float f0 = cc0 - (float)lo0;

    const bool v1 = (c1 >= -1.0f) && (c1 <= szf);
    float cc1 = fminf(fmaxf(c1, 0.0f), szf - 1.0f);
    const int lo1 = (int)floorf(cc1);
    const int hi1 = min(lo1 + 1, size - 1);
    const float f1 = cc1 - (float)lo1;

    base = lo0;
    if (v0) { w[0]         += 1.0f - f0; w[hi0 - lo0] += f0; }
    if (v1) { w[lo1 - lo0] += 1.0f - f1; w[hi1 - lo0] += f1; }
}

__device__ __forceinline__ float sel4(int i, float a, float b, float c, float d) {
    return (i == 0) ? a : ((i == 1) ? b : ((i == 2) ? c : d));
}

__device__ __forceinline__ __half2 h2_from_bits(int b) {
    __half2 h;
    *reinterpret_cast<int*>(&h) = b;
    return h;
}

// ---------------------------------------------------------------------------
// Gather: grid (R, NCELL), block (32, PD). Warp = one (cell, pd) task.
// R13 structure; inner loop chains 4 taps in fp16 (HMUL2 + 3xHFMA2) and
// flushes to fp32 once per iteration (halves the cvt+add flush traffic).
// ---------------------------------------------------------------------------
__global__ void __launch_bounds__(32 * PD) roi3d_gather(const float* __restrict__ rois,
                                                        const uint2* __restrict__ fp,
                                                        float* __restrict__ out) {
    __shared__ int2 taps[PD][TAPCAP];

    const int r    = blockIdx.x;
    const int cell = blockIdx.y;
    const int ph   = cell / PW;
    const int pw   = cell - ph * PW;
    const int pd   = threadIdx.y;          // warp id = pd
    const int lane = threadIdx.x;

    const float* roi = rois + r * 7;
    const int   b  = (int)__ldg(roi);
    const float x1 = __ldg(roi + 1) * 0.25f, y1 = __ldg(roi + 2) * 0.25f;
    const float z1 = __ldg(roi + 3) * 0.25f;
    const float x2 = __ldg(roi + 4) * 0.25f, y2 = __ldg(roi + 5) * 0.25f;
    const float z2 = __ldg(roi + 6) * 0.25f;
    const float sz = fmaxf(z2 - z1, 1.0f) * (1.0f / (PD * 2));
    const float sy = fmaxf(y2 - y1, 1.0f) * (1.0f / (PH * 2));
    const float sx = fmaxf(x2 - x1, 1.0f) * (1.0f / (PW * 2));
    const int bbase = b * DHW;

    const float zc0 = z1 + ((float)(pd * 2) + 0.5f) * sz;
    const float yc0 = y1 + ((float)(ph * 2) + 0.5f) * sy;
    const float xc0 = x1 + ((float)(pw * 2) + 0.5f) * sx;

    int bz, by, bx;
    float wz[4], wy[4], wx[4];
    axis_taps(zc0, zc0 + sz, D_, bz, wz);
    axis_taps(yc0, yc0 + sy, H_, by, wy);
    axis_taps(xc0, xc0 + sx, W_, bx, wx);
    wz[0] *= 0.125f; wz[1] *= 0.125f; wz[2] *= 0.125f; wz[3] *= 0.125f;

    // lane's combo decomposition: combo = zi*16 + yi*4 + xi; lane -> {lane, lane+32}
    const int zi0 = lane >> 4;             // 0..1 (combo B: zi0 + 2)
    const int yi0 = (lane >> 2) & 3;
    const int xi  = lane & 3;

    // direct IMAD offsets (uint2 units: voxel * 32)
    const int HW32 = HW_ * 32;
    const int W32  = W_ * 32;
    const int o0 = (bbase + bz * HW_) * 32 + zi0 * HW32 + (by + yi0) * W32
                 + (bx + xi) * 32;
    const int o1 = o0 + 2 * HW32;

    int2* wlist = taps[pd];

    // ---- cooperative compaction (weights packed as duplicated half2) ----
    int nt = 0;
    {
        const float wyx = sel4(yi0, wy[0], wy[1], wy[2], wy[3]) * wx[xi];

        const float w0 = (zi0 == 0 ? wz[0] : wz[1]) * wyx;
        unsigned bal = __ballot_sync(0xffffffffu, w0 != 0.0f);
        if (w0 != 0.0f) {
            int slot = __popc(bal & ((1u << lane) - 1u));
            __half2 wh = __float2half2_rn(w0);
            wlist[slot] = make_int2(o0, *reinterpret_cast<int*>(&wh));
        }
        nt = __popc(bal);

        const float w1 = (zi0 == 0 ? wz[2] : wz[3]) * wyx;
        unsigned bal1 = __ballot_sync(0xffffffffu, w1 != 0.0f);
        if (w1 != 0.0f) {
            int slot = nt + __popc(bal1 & ((1u << lane) - 1u));
            __half2 wh = __float2half2_rn(w1);
            wlist[slot] = make_int2(o1, *reinterpret_cast<int*>(&wh));
        }
        nt += __popc(bal1);
    }
    if (lane < 3) wlist[nt + lane] = make_int2(0, 0);   // zero-weight pad
    const int nt4 = (nt + 3) & ~3;
    __syncwarp();

    // ---- branch-free gather: 4-tap fp16 chain, one fp32 flush per iter ----
    const uint2* __restrict__ fpl = fp + lane;
    float4 acc = make_float4(0.0f, 0.0f, 0.0f, 0.0f);

    for (int j = 0; j < nt4; j += 4) {
        const int4 p0 = *reinterpret_cast<const int4*>(&wlist[j]);     // taps 0,1
        const int4 p1 = *reinterpret_cast<const int4*>(&wlist[j + 2]); // taps 2,3
        const uint2 v0 = __ldg(fpl + p0.x);
        const uint2 v1 = __ldg(fpl + p0.z);
        const uint2 v2 = __ldg(fpl + p1.x);
        const uint2 v3 = __ldg(fpl + p1.z);

        const __half2 w0 = h2_from_bits(p0.y);
        const __half2 w1 = h2_from_bits(p0.w);
        const __half2 w2 = h2_from_bits(p1.y);
        const __half2 w3 = h2_from_bits(p1.w);

        __half2 h01 = __hmul2(h2_from_bits((int)v0.x), w0);
        __half2 h23 = __hmul2(h2_from_bits((int)v0.y), w0);
        h01 = __hfma2(h2_from_bits((int)v1.x), w1, h01);
        h23 = __hfma2(h2_from_bits((int)v1.y), w1, h23);
        h01 = __hfma2(h2_from_bits((int)v2.x), w2, h01);
        h23 = __hfma2(h2_from_bits((int)v2.y), w2, h23);
        h01 = __hfma2(h2_from_bits((int)v3.x), w3, h01);
        h23 = __hfma2(h2_from_bits((int)v3.y), w3, h23);

        // single fp32 flush for the 4-tap group
        float2 f;
        f = __half22float2(h01); acc.x += f.x; acc.y += f.y;
        f = __half22float2(h23); acc.z += f.x; acc.w += f.y;
    }

    // ---- direct stores: out[r][c][pd][ph][pw], c = lane*4 ----
    const int ob = ((r * C_ + lane * 4) * PD + pd) * NCELL + cell;
    out[ob]                  = acc.x;
    out[ob + PD * NCELL]     = acc.y;
    out[ob + 2 * PD * NCELL] = acc.z;
    out[ob + 3 * PD * NCELL] = acc.w;
}

// ---------------------------------------------------------------------------
extern "C" void kernel_launch(void* const* d_in, const int* in_sizes, int n_in,
                              void* d_out, int out_size) {
    const float* features = (const float*)d_in[0];
    const float* rois     = (const float*)d_in[1];
    float*       out      = (float*)d_out;

    __half* feat_t = nullptr;
    cudaGetSymbolAddress((void**)&feat_t, g_feat_t);

    // 1) NCDHW fp32 -> NDHWC fp16
    dim3 tg(DHW / 64, C_ / 64, N_);
    dim3 tb(32, 8);
    transpose_ndhwc_h<<<tg, tb>>>(features, feat_t);

    // 2) Gather
    dim3 rg(R_, NCELL);
    dim3 rb(32, PD);
    roi3d_gather<<<rg, rb>>>(rois, (const uint2*)feat_t, out);
}